// round 12
// baseline (speedup 1.0000x reference)
#include <cuda_runtime.h>
#include <math.h>
#include <stdint.h>

#define BB 32
#define SS 4096
#define II 512
#define HH 512
#define NCH 8
#define CHUNK (SS / NCH)      // 512 positions per block
#define WPOS (CHUNK / 8)      // 64 positions per warp
#define NTHREADS 256
#define NEG_INF_F (-1e18f)
#define HSPLIT 8
#define PGRP 4                // batches per project block

// -------- persistent device scratch (no allocations allowed) --------
__device__ float g_part[2 * HSPLIT * II];  // [mat][hs][i] partials
__device__ float g_w2[II];                 // Wk^T @ Wout
__device__ float g_qoff[BB];               // per-batch additive score offset
__device__ float g_kacc[BB * II];          // atomic accumulator: sum exp(s)*key
__device__ float g_lacc[BB];               // atomic accumulator: sum exp(s)

// ============================================================
// Kernel A1: partial projected-weight vectors + zero accumulators.
// ============================================================
__global__ void __launch_bounds__(256) prep_partial(
    const float* __restrict__ Wk, const float* __restrict__ Wq,
    const float* __restrict__ Wout)
{
    const int blk = blockIdx.x;
    const int tid = threadIdx.x;

    // zero the atomic accumulators for this graph replay
    if (blk < 64) g_kacc[blk * 256 + tid] = 0.f;
    if (blk == 64 && tid < BB) g_lacc[tid] = 0.f;

    const int mat = blk >> 7;
    const int rem = blk & 127;
    const int hs  = rem >> 4;
    const int ig  = rem & 15;
    const int i0  = ig * 32;
    const int h0  = hs * 64;
    const int il   = tid & 31;
    const int hsub = tid >> 5;

    const float* W = mat ? Wq : Wk;

    __shared__ float wout_sh[64];
    __shared__ float red[256];
    if (tid < 64) wout_sh[tid] = Wout[h0 + tid];
    __syncthreads();

    float acc = 0.f;
    #pragma unroll
    for (int k = 0; k < 8; k++) {
        int hl = hsub * 8 + k;
        acc += W[(size_t)(h0 + hl) * II + i0 + il] * wout_sh[hl];
    }
    red[tid] = acc;
    __syncthreads();
    if (tid < 128) red[tid] += red[tid + 128];
    __syncthreads();
    if (tid < 64) red[tid] += red[tid + 64];
    __syncthreads();
    if (tid < 32)
        g_part[(mat * HSPLIT + hs) * II + i0 + tid] = red[tid] + red[tid + 32];
}

// ============================================================
// Kernel A2: combine partials -> g_w2, g_qoff (unchanged).
// ============================================================
__global__ void __launch_bounds__(512) prep_combine(
    const float* __restrict__ query,
    const float* __restrict__ bq, const float* __restrict__ bk,
    const float* __restrict__ Wout)
{
    const int tid = threadIdx.x;
    if (blockIdx.x == 32) {
        float s = 0.f;
        #pragma unroll
        for (int hs = 0; hs < HSPLIT; hs++)
            s += g_part[hs * II + tid];
        g_w2[tid] = s;
        return;
    }
    const int b = blockIdx.x;
    __shared__ float wq2_sh[II];
    __shared__ float red[512];

    float s = 0.f;
    #pragma unroll
    for (int hs = 0; hs < HSPLIT; hs++)
        s += g_part[(HSPLIT + hs) * II + tid];
    wq2_sh[tid] = s;

    red[tid] = Wout[tid] * (bq[tid] + bk[tid]);
    __syncthreads();
    for (int off = 256; off > 0; off >>= 1) {
        if (tid < off) red[tid] += red[tid + off];
        __syncthreads();
    }
    float cbias = red[0];
    __syncthreads();

    red[tid] = query[(size_t)b * II + tid] * wq2_sh[tid];
    __syncthreads();
    for (int off = 256; off > 0; off >>= 1) {
        if (tid < off) red[tid] += red[tid + off];
        __syncthreads();
    }
    if (tid == 0) g_qoff[b] = red[0] + cbias;
}

// ============================================================
// Kernel B: pure-register streaming pass (unchanged from R10).
// ============================================================
__global__ void __launch_bounds__(NTHREADS, 2) main_pass(
    const float* __restrict__ key,
    const int* __restrict__ mask,
    float* __restrict__ out)
{
    const int b = blockIdx.x / NCH;
    const int c = blockIdx.x % NCH;
    const int tid = threadIdx.x;
    const int lane = tid & 31;
    const int warp = tid >> 5;
    const int s0 = c * CHUNK;
    const int sw = s0 + warp * WPOS;

    const float4* keyw = (const float4*)(key + (size_t)b * SS * II + (size_t)sw * II);

    const int m0 = mask[(size_t)b * SS + sw + lane];
    const int m1 = mask[(size_t)b * SS + sw + 32 + lane];

    const float4* w24 = (const float4*)g_w2;
    float4 w2r[4];
    #pragma unroll
    for (int j = 0; j < 4; j++) w2r[j] = w24[lane + 32 * j];

    const float qoff = g_qoff[b];

    float4 kb[4];
    #pragma unroll
    for (int j = 0; j < 4; j++) kb[j] = make_float4(0.f, 0.f, 0.f, 0.f);
    float l = 0.f;
    float sc0 = NEG_INF_F, sc1 = NEG_INF_F;

    float4 KV[4][4];
    #pragma unroll
    for (int r = 0; r < 4; r++) {
        #pragma unroll
        for (int j = 0; j < 4; j++)
            KV[r][j] = keyw[(size_t)r * 128 + lane + 32 * j];
    }

    #pragma unroll 1
    for (int p = 0; p < WPOS; p += 4) {
        #pragma unroll
        for (int q = 0; q < 4; q++) {
            const int pp = p + q;
            float acc = KV[q][0].x * w2r[0].x + KV[q][0].y * w2r[0].y
                      + KV[q][0].z * w2r[0].z + KV[q][0].w * w2r[0].w;
            #pragma unroll
            for (int j = 1; j < 4; j++)
                acc += KV[q][j].x * w2r[j].x + KV[q][j].y * w2r[j].y
                     + KV[q][j].z * w2r[j].z + KV[q][j].w * w2r[j].w;
            #pragma unroll
            for (int off = 16; off > 0; off >>= 1)
                acc += __shfl_xor_sync(0xffffffffu, acc, off);

            const int mv = __shfl_sync(0xffffffffu, (pp & 32) ? m1 : m0, pp & 31);
            const float e = mv ? 0.f : __expf(acc);
            const float scst = mv ? NEG_INF_F : acc + qoff;
            if (lane == (pp & 31)) {
                if (pp < 32) sc0 = scst; else sc1 = scst;
            }
            l += e;
            #pragma unroll
            for (int j = 0; j < 4; j++) {
                kb[j].x += e * KV[q][j].x;
                kb[j].y += e * KV[q][j].y;
                kb[j].z += e * KV[q][j].z;
                kb[j].w += e * KV[q][j].w;
            }
            if (pp + 4 < WPOS) {
                #pragma unroll
                for (int j = 0; j < 4; j++)
                    KV[q][j] = keyw[(size_t)(pp + 4) * 128 + lane + 32 * j];
            }
        }
    }

    out[(size_t)BB * HH + (size_t)b * SS + sw + lane] = sc0;
    out[(size_t)BB * HH + (size_t)b * SS + sw + 32 + lane] = sc1;

    __shared__ float stage[8 * II];
    __shared__ float l_sh[8];
    float4* st4 = (float4*)(stage + warp * II);
    #pragma unroll
    for (int j = 0; j < 4; j++) st4[lane + 32 * j] = kb[j];
    if (lane == 0) l_sh[warp] = l;
    __syncthreads();

    float t0 = 0.f, t1 = 0.f;
    #pragma unroll
    for (int w = 0; w < 8; w++) {
        t0 += stage[w * II + tid];
        t1 += stage[w * II + tid + 256];
    }
    atomicAdd(&g_kacc[b * II + tid], t0);
    atomicAdd(&g_kacc[b * II + tid + 256], t1);
    if (tid == 0) {
        float lt = 0.f;
        #pragma unroll
        for (int w = 0; w < 8; w++) lt += l_sh[w];
        atomicAdd(&g_lacc[b], lt);
    }
}

// ============================================================
// Kernel C: barrier-free projection. grid = 8 groups * 64
// h-blocks = 512. No smem, no syncthreads: all loads issued
// up-front into registers, normalize at the store.
// ============================================================
__global__ void __launch_bounds__(256) project(
    const float* __restrict__ Wk, const float* __restrict__ bk,
    float* __restrict__ out)
{
    const int tid = threadIdx.x;
    const int lane = tid & 31;
    const int warp = tid >> 5;
    const int grp = blockIdx.x >> 6;          // 0..7
    const int hb  = blockIdx.x & 63;          // 0..63
    const int h = hb * 8 + warp;
    const int b0 = grp * PGRP;

    // independent loads, all in flight together
    const float4* w4 = (const float4*)(Wk + (size_t)h * II);
    float4 wr[4];
    #pragma unroll
    for (int j = 0; j < 4; j++) wr[j] = w4[lane + j * 32];

    float4 kv[PGRP][4];
    #pragma unroll
    for (int bb = 0; bb < PGRP; bb++) {
        const float4* kb4 = (const float4*)(g_kacc + (size_t)(b0 + bb) * II);
        #pragma unroll
        for (int j = 0; j < 4; j++) kv[bb][j] = kb4[lane + j * 32];
    }

    float linv[PGRP];
    #pragma unroll
    for (int bb = 0; bb < PGRP; bb++) linv[bb] = g_lacc[b0 + bb];

    const float bkh = bk[h];

    float acc[PGRP];
    #pragma unroll
    for (int bb = 0; bb < PGRP; bb++) {
        float a = 0.f;
        #pragma unroll
        for (int j = 0; j < 4; j++)
            a += wr[j].x * kv[bb][j].x + wr[j].y * kv[bb][j].y
               + wr[j].z * kv[bb][j].z + wr[j].w * kv[bb][j].w;
        acc[bb] = a;
    }
    #pragma unroll
    for (int off = 16; off > 0; off >>= 1) {
        #pragma unroll
        for (int bb = 0; bb < PGRP; bb++)
            acc[bb] += __shfl_down_sync(0xffffffffu, acc[bb], off);
    }
    if (lane == 0) {
        #pragma unroll
        for (int bb = 0; bb < PGRP; bb++)
            out[(b0 + bb) * HH + h] = acc[bb] / linv[bb] + bkh;
    }
}

// ============================================================
extern "C" void kernel_launch(void* const* d_in, const int* in_sizes, int n_in,
                              void* d_out, int out_size) {
    const float* query = (const float*)d_in[0];
    const float* key   = (const float*)d_in[1];
    const int*   mask  = (const int*)d_in[2];
    const float* Wq   = (const float*)d_in[3];
    const float* bq   = (const float*)d_in[4];
    const float* Wk   = (const float*)d_in[5];
    const float* bk   = (const float*)d_in[6];
    const float* Wout = (const float*)d_in[7];
    float* out = (float*)d_out;

    prep_partial<<<256, 256>>>(Wk, Wq, Wout);
    prep_combine<<<33, 512>>>(query, bq, bk, Wout);
    main_pass<<<BB * NCH, NTHREADS>>>(key, mask, out);
    project<<<8 * (HH / 8), 256>>>(Wk, bk, out);
}

// round 13
// speedup vs baseline: 1.0458x; 1.0458x over previous
#include <cuda_runtime.h>
#include <math.h>
#include <stdint.h>

#define BB 32
#define SS 4096
#define II 512
#define HH 512
#define NCH 8
#define CHUNK (SS / NCH)      // 512 positions per block
#define WPOS (CHUNK / 8)      // 64 positions per warp
#define NTHREADS 256
#define NEG_INF_F (-1e18f)
#define HSPLIT 8
#define PGRP 4                // batches per project block

// -------- persistent device scratch (no allocations allowed) --------
// g_w2 / g_wq2 are accumulated by atomicAdd in prep and zeroed for the
// NEXT replay by project (which never reads them). Zero-initialized at
// module load, so the first (correctness) run is also correct.
__device__ float g_w2[II];                 // Wk^T @ Wout   (atomic accum)
__device__ float g_wq2[II];                // Wq^T @ Wout   (atomic accum)
__device__ float g_cbias;                  // Wout . (bq + bk)
__device__ float g_kacc[BB * II];          // atomic accumulator: sum exp(s)*key
__device__ float g_lacc[BB];               // atomic accumulator: sum exp(s)

// ============================================================
// Kernel A: fused prep. 256 blocks: mat(2) x hsplit(8) x ig(16).
// Block-reduced partials atomicAdd'ed into g_w2 / g_wq2.
// Also zeroes g_kacc/g_lacc; block 65 computes g_cbias.
// ============================================================
__global__ void __launch_bounds__(256) prep(
    const float* __restrict__ Wk, const float* __restrict__ Wq,
    const float* __restrict__ Wout,
    const float* __restrict__ bq, const float* __restrict__ bk)
{
    const int blk = blockIdx.x;
    const int tid = threadIdx.x;

    // zero the softmax accumulators for this replay
    if (blk < 64) g_kacc[blk * 256 + tid] = 0.f;
    if (blk == 64 && tid < BB) g_lacc[tid] = 0.f;

    const int mat = blk >> 7;
    const int rem = blk & 127;
    const int hs  = rem >> 4;
    const int ig  = rem & 15;
    const int i0  = ig * 32;
    const int h0  = hs * 64;
    const int il   = tid & 31;
    const int hsub = tid >> 5;

    const float* W = mat ? Wq : Wk;
    float* dst = mat ? g_wq2 : g_w2;

    __shared__ float wout_sh[64];
    __shared__ float red[256];
    if (tid < 64) wout_sh[tid] = Wout[h0 + tid];
    __syncthreads();

    float acc = 0.f;
    #pragma unroll
    for (int k = 0; k < 8; k++) {
        int hl = hsub * 8 + k;
        acc += W[(size_t)(h0 + hl) * II + i0 + il] * wout_sh[hl];
    }
    red[tid] = acc;
    __syncthreads();
    if (tid < 128) red[tid] += red[tid + 128];
    __syncthreads();
    if (tid < 64) red[tid] += red[tid + 64];
    __syncthreads();
    if (tid < 32)
        atomicAdd(&dst[i0 + tid], red[tid] + red[tid + 32]);

    // block 65: cbias = Wout . (bq + bk)
    if (blk == 65) {
        __syncthreads();
        red[tid] = Wout[tid] * (bq[tid] + bk[tid])
                 + Wout[tid + 256] * (bq[tid + 256] + bk[tid + 256]);
        __syncthreads();
        for (int off = 128; off > 0; off >>= 1) {
            if (tid < off) red[tid] += red[tid + off];
            __syncthreads();
        }
        if (tid == 0) g_cbias = red[0];
    }
}

// ============================================================
// Kernel B: pure-register streaming pass. Computes qoff[b]
// in-block at the end (query . g_wq2 + g_cbias), adds it to
// the stored scores (masked -1e18 unaffected in fp32).
// ============================================================
__global__ void __launch_bounds__(NTHREADS, 2) main_pass(
    const float* __restrict__ key,
    const int* __restrict__ mask,
    const float* __restrict__ query,
    float* __restrict__ out)
{
    const int b = blockIdx.x / NCH;
    const int c = blockIdx.x % NCH;
    const int tid = threadIdx.x;
    const int lane = tid & 31;
    const int warp = tid >> 5;
    const int s0 = c * CHUNK;
    const int sw = s0 + warp * WPOS;

    const float4* keyw = (const float4*)(key + (size_t)b * SS * II + (size_t)sw * II);

    const int m0 = mask[(size_t)b * SS + sw + lane];
    const int m1 = mask[(size_t)b * SS + sw + 32 + lane];

    const float4* w24 = (const float4*)g_w2;
    float4 w2r[4];
    #pragma unroll
    for (int j = 0; j < 4; j++) w2r[j] = w24[lane + 32 * j];

    float4 kb[4];
    #pragma unroll
    for (int j = 0; j < 4; j++) kb[j] = make_float4(0.f, 0.f, 0.f, 0.f);
    float l = 0.f;
    float sc0 = NEG_INF_F, sc1 = NEG_INF_F;

    float4 KV[4][4];
    #pragma unroll
    for (int r = 0; r < 4; r++) {
        #pragma unroll
        for (int j = 0; j < 4; j++)
            KV[r][j] = keyw[(size_t)r * 128 + lane + 32 * j];
    }

    #pragma unroll 1
    for (int p = 0; p < WPOS; p += 4) {
        #pragma unroll
        for (int q = 0; q < 4; q++) {
            const int pp = p + q;
            float acc = KV[q][0].x * w2r[0].x + KV[q][0].y * w2r[0].y
                      + KV[q][0].z * w2r[0].z + KV[q][0].w * w2r[0].w;
            #pragma unroll
            for (int j = 1; j < 4; j++)
                acc += KV[q][j].x * w2r[j].x + KV[q][j].y * w2r[j].y
                     + KV[q][j].z * w2r[j].z + KV[q][j].w * w2r[j].w;
            #pragma unroll
            for (int off = 16; off > 0; off >>= 1)
                acc += __shfl_xor_sync(0xffffffffu, acc, off);

            const int mv = __shfl_sync(0xffffffffu, (pp & 32) ? m1 : m0, pp & 31);
            const float e = mv ? 0.f : __expf(acc);
            const float scst = mv ? NEG_INF_F : acc;
            if (lane == (pp & 31)) {
                if (pp < 32) sc0 = scst; else sc1 = scst;
            }
            l += e;
            #pragma unroll
            for (int j = 0; j < 4; j++) {
                kb[j].x += e * KV[q][j].x;
                kb[j].y += e * KV[q][j].y;
                kb[j].z += e * KV[q][j].z;
                kb[j].w += e * KV[q][j].w;
            }
            if (pp + 4 < WPOS) {
                #pragma unroll
                for (int j = 0; j < 4; j++)
                    KV[q][j] = keyw[(size_t)(pp + 4) * 128 + lane + 32 * j];
            }
        }
    }

    // ---- qoff = query[b] . g_wq2 + cbias (block-redundant, 1 barrier) ----
    __shared__ float q_sh[8];
    float qp = query[(size_t)b * II + tid] * g_wq2[tid]
             + query[(size_t)b * II + tid + 256] * g_wq2[tid + 256];
    #pragma unroll
    for (int off = 16; off > 0; off >>= 1)
        qp += __shfl_xor_sync(0xffffffffu, qp, off);
    if (lane == 0) q_sh[warp] = qp;
    __syncthreads();
    float qoff = g_cbias;
    #pragma unroll
    for (int w = 0; w < 8; w++) qoff += q_sh[w];

    // attn_weight stores (masked -1e18 + qoff == -1e18 exactly in fp32)
    out[(size_t)BB * HH + (size_t)b * SS + sw + lane] = sc0 + qoff;
    out[(size_t)BB * HH + (size_t)b * SS + sw + 32 + lane] = sc1 + qoff;

    // ---- block merge of kbar partials, then global atomics ----
    __shared__ float stage[8 * II];
    __shared__ float l_sh[8];
    float4* st4 = (float4*)(stage + warp * II);
    #pragma unroll
    for (int j = 0; j < 4; j++) st4[lane + 32 * j] = kb[j];
    if (lane == 0) l_sh[warp] = l;
    __syncthreads();

    float t0 = 0.f, t1 = 0.f;
    #pragma unroll
    for (int w = 0; w < 8; w++) {
        t0 += stage[w * II + tid];
        t1 += stage[w * II + tid + 256];
    }
    atomicAdd(&g_kacc[b * II + tid], t0);
    atomicAdd(&g_kacc[b * II + tid + 256], t1);
    if (tid == 0) {
        float lt = 0.f;
        #pragma unroll
        for (int w = 0; w < 8; w++) lt += l_sh[w];
        atomicAdd(&g_lacc[b], lt);
    }
}

// ============================================================
// Kernel C: barrier-free projection (unchanged), plus blocks
// 0/1 zero g_w2/g_wq2 for the NEXT graph replay (no project
// block reads them).
// ============================================================
__global__ void __launch_bounds__(256) project(
    const float* __restrict__ Wk, const float* __restrict__ bk,
    float* __restrict__ out)
{
    const int tid = threadIdx.x;
    const int lane = tid & 31;
    const int warp = tid >> 5;
    const int grp = blockIdx.x >> 6;          // 0..7
    const int hb  = blockIdx.x & 63;          // 0..63
    const int h = hb * 8 + warp;
    const int b0 = grp * PGRP;

    // cross-replay zeroing of the prep accumulators
    if (blockIdx.x == 0) { g_w2[tid] = 0.f; g_w2[tid + 256] = 0.f; }
    if (blockIdx.x == 1) { g_wq2[tid] = 0.f; g_wq2[tid + 256] = 0.f; }

    const float4* w4 = (const float4*)(Wk + (size_t)h * II);
    float4 wr[4];
    #pragma unroll
    for (int j = 0; j < 4; j++) wr[j] = w4[lane + j * 32];

    float4 kv[PGRP][4];
    #pragma unroll
    for (int bb = 0; bb < PGRP; bb++) {
        const float4* kb4 = (const float4*)(g_kacc + (size_t)(b0 + bb) * II);
        #pragma unroll
        for (int j = 0; j < 4; j++) kv[bb][j] = kb4[lane + j * 32];
    }

    float lden[PGRP];
    #pragma unroll
    for (int bb = 0; bb < PGRP; bb++) lden[bb] = g_lacc[b0 + bb];

    const float bkh = bk[h];

    float acc[PGRP];
    #pragma unroll
    for (int bb = 0; bb < PGRP; bb++) {
        float a = 0.f;
        #pragma unroll
        for (int j = 0; j < 4; j++)
            a += wr[j].x * kv[bb][j].x + wr[j].y * kv[bb][j].y
               + wr[j].z * kv[bb][j].z + wr[j].w * kv[bb][j].w;
        acc[bb] = a;
    }
    #pragma unroll
    for (int off = 16; off > 0; off >>= 1) {
        #pragma unroll
        for (int bb = 0; bb < PGRP; bb++)
            acc[bb] += __shfl_down_sync(0xffffffffu, acc[bb], off);
    }
    if (lane == 0) {
        #pragma unroll
        for (int bb = 0; bb < PGRP; bb++)
            out[(b0 + bb) * HH + h] = acc[bb] / lden[bb] + bkh;
    }
}

// ============================================================
extern "C" void kernel_launch(void* const* d_in, const int* in_sizes, int n_in,
                              void* d_out, int out_size) {
    const float* query = (const float*)d_in[0];
    const float* key   = (const float*)d_in[1];
    const int*   mask  = (const int*)d_in[2];
    const float* Wq   = (const float*)d_in[3];
    const float* bq   = (const float*)d_in[4];
    const float* Wk   = (const float*)d_in[5];
    const float* bk   = (const float*)d_in[6];
    const float* Wout = (const float*)d_in[7];
    float* out = (float*)d_out;

    prep<<<256, 256>>>(Wk, Wq, Wout, bq, bk);
    main_pass<<<BB * NCH, NTHREADS>>>(key, mask, query, out);
    project<<<8 * (HH / 8), 256>>>(Wk, bk, out);
}